// round 1
// baseline (speedup 1.0000x reference)
#include <cuda_runtime.h>

#define BB 32
#define QQ 900
#define CCLS 91
#define TT 30
#define TBLK 256
#define ICH 57          // 16 * 57 = 912 >= 900
#define ITILES 16
#define BIGV 1e9f

// Scratch (device globals; no allocation allowed)
__device__ float g_table[BB * QQ * CCLS];   // focal class-cost table [B,Q,C]
__device__ int   g_label[BB * QQ];
__device__ int   g_mask[BB * QQ];

// ---------------------------------------------------------------------------
// Kernel 1: pseudo labels + mask. GIoU vs targets must match the reference's
// IEEE fp32 op order exactly (no FMA contraction, rn division) because a mask
// flip swaps a ~O(10) value for 1e9 in 900 output entries.
// ---------------------------------------------------------------------------
__global__ void pseudo_kernel(const float* __restrict__ logits_base,
                              const float4* __restrict__ boxes_base,
                              const float4* __restrict__ targets,
                              float* __restrict__ out_mask, int write_mask)
{
    int tid = blockIdx.x * blockDim.x + threadIdx.x;
    if (tid >= BB * QQ) return;
    int b = tid / QQ;

    // argmax over logits (sigmoid is strictly monotone -> same argmax)
    const float* row = logits_base + (size_t)tid * CCLS;
    float best = row[0];
    int bl = 0;
    for (int c = 1; c < CCLS; c++) {
        float x = row[c];
        if (x > best) { best = x; bl = c; }
    }
    int keep = (best > 0.0f);   // sigmoid(best) > 0.5

    // base box -> xyxy (exact op order, no contraction)
    float4 bb = boxes_base[tid];
    float bx0 = __fsub_rn(bb.x, __fmul_rn(0.5f, bb.z));
    float by0 = __fsub_rn(bb.y, __fmul_rn(0.5f, bb.w));
    float bx1 = __fadd_rn(bb.x, __fmul_rn(0.5f, bb.z));
    float by1 = __fadd_rn(bb.y, __fmul_rn(0.5f, bb.w));
    float barea = __fmul_rn(__fsub_rn(bx1, bx0), __fsub_rn(by1, by0));

    for (int t = 0; t < TT; t++) {
        float4 tb = targets[b * TT + t];
        float tx0 = __fsub_rn(tb.x, __fmul_rn(0.5f, tb.z));
        float ty0 = __fsub_rn(tb.y, __fmul_rn(0.5f, tb.w));
        float tx1 = __fadd_rn(tb.x, __fmul_rn(0.5f, tb.z));
        float ty1 = __fadd_rn(tb.y, __fmul_rn(0.5f, tb.w));
        float tarea = __fmul_rn(__fsub_rn(tx1, tx0), __fsub_rn(ty1, ty0));

        float lx = fmaxf(bx0, tx0), ly = fmaxf(by0, ty0);
        float rx = fminf(bx1, tx1), ry = fminf(by1, ty1);
        float w = fmaxf(__fsub_rn(rx, lx), 0.0f);
        float h = fmaxf(__fsub_rn(ry, ly), 0.0f);
        float inter = __fmul_rn(w, h);
        float uni = __fsub_rn(__fadd_rn(barea, tarea), inter);
        float iou = __fdiv_rn(inter, uni);

        float clx = fminf(bx0, tx0), cly = fminf(by0, ty0);
        float crx = fmaxf(bx1, tx1), cry = fmaxf(by1, ty1);
        float cw = fmaxf(__fsub_rn(crx, clx), 0.0f);
        float ch = fmaxf(__fsub_rn(cry, cly), 0.0f);
        float ac = __fmul_rn(cw, ch);
        float g = __fsub_rn(iou, __fdiv_rn(__fsub_rn(ac, uni), ac));
        keep = keep && (-g > -0.1f);   // reference: all(-giou > BBOX_THRESH)
    }

    g_label[tid] = bl;
    g_mask[tid] = keep;
    if (write_mask) out_mask[tid] = keep ? 1.0f : 0.0f;
}

// ---------------------------------------------------------------------------
// Kernel 2: focal class-cost table [B,Q,C]. Precomputing this removes exp+2log
// per output entry (52M MUFUs) -> one 4B gather instead.
// ---------------------------------------------------------------------------
__global__ void table_kernel(const float* __restrict__ pred_logits)
{
    int idx = blockIdx.x * blockDim.x + threadIdx.x;
    if (idx >= BB * QQ * CCLS) return;
    float x = pred_logits[idx];
    float p = 1.0f / (1.0f + expf(-x));
    float omp = 1.0f - p;
    float pos = 0.25f * omp * omp * (-logf(p + 1e-8f));
    float neg = 0.75f * p * p * (-logf(omp + 1e-8f));
    g_table[idx] = pos - neg;
}

// ---------------------------------------------------------------------------
// Kernel 3: cost matrix. Thread = 4 consecutive j (pseudo) columns held in
// registers; i rows staged in SMEM (broadcast reads). float4 coalesced stores.
// ---------------------------------------------------------------------------
__global__ void __launch_bounds__(TBLK)
cost_kernel(const float4* __restrict__ pred_boxes,
            const float4* __restrict__ boxes_base,
            float* __restrict__ out)
{
    __shared__ float s_cx[ICH], s_cy[ICH], s_w[ICH], s_h[ICH];
    __shared__ float s_x0[ICH], s_y0[ICH], s_x1[ICH], s_y1[ICH], s_a[ICH];

    int b = blockIdx.y;
    int i0 = blockIdx.x * ICH;

    for (int k = threadIdx.x; k < ICH; k += TBLK) {
        int i = i0 + k;
        float4 bx = (i < QQ) ? pred_boxes[b * QQ + i] : make_float4(0.f, 0.f, 0.f, 0.f);
        float hw = 0.5f * bx.z, hh = 0.5f * bx.w;
        float x0 = bx.x - hw, y0 = bx.y - hh;
        float x1 = bx.x + hw, y1 = bx.y + hh;
        s_cx[k] = bx.x; s_cy[k] = bx.y; s_w[k] = bx.z; s_h[k] = bx.w;
        s_x0[k] = x0; s_y0[k] = y0; s_x1[k] = x1; s_y1[k] = y1;
        s_a[k] = (x1 - x0) * (y1 - y0);
    }
    __syncthreads();

    int tid = threadIdx.x;
    if (tid >= QQ / 4) return;      // 225 active threads (900 = 4*225)
    int j0 = tid * 4;

    float jcx[4], jcy[4], jw[4], jh[4];
    float jx0[4], jy0[4], jx1[4], jy1[4], ja[4];
    int jlab[4], jm[4];
#pragma unroll
    for (int jj = 0; jj < 4; jj++) {
        int j = j0 + jj;
        float4 bb = boxes_base[b * QQ + j];
        float hw = 0.5f * bb.z, hh = 0.5f * bb.w;
        jcx[jj] = bb.x; jcy[jj] = bb.y; jw[jj] = bb.z; jh[jj] = bb.w;
        jx0[jj] = bb.x - hw; jy0[jj] = bb.y - hh;
        jx1[jj] = bb.x + hw; jy1[jj] = bb.y + hh;
        ja[jj] = (jx1[jj] - jx0[jj]) * (jy1[jj] - jy0[jj]);
        jlab[jj] = g_label[b * QQ + j];
        jm[jj] = g_mask[b * QQ + j];
    }

    float4* out4 = (float4*)out;
    int imax = min(QQ, i0 + ICH);
    for (int i = i0; i < imax; i++) {
        int k = i - i0;
        float icx = s_cx[k], icy = s_cy[k], iw = s_w[k], ih = s_h[k];
        float ix0 = s_x0[k], iy0 = s_y0[k], ix1 = s_x1[k], iy1 = s_y1[k];
        float ia = s_a[k];
        const float* trow = g_table + (size_t)(b * QQ + i) * CCLS;

        float r[4];
#pragma unroll
        for (int jj = 0; jj < 4; jj++) {
            float l1 = fabsf(icx - jcx[jj]) + fabsf(icy - jcy[jj])
                     + fabsf(iw - jw[jj]) + fabsf(ih - jh[jj]);

            float lx = fmaxf(ix0, jx0[jj]), ly = fmaxf(iy0, jy0[jj]);
            float rx = fminf(ix1, jx1[jj]), ry = fminf(iy1, jy1[jj]);
            float w = fmaxf(rx - lx, 0.0f);
            float h = fmaxf(ry - ly, 0.0f);
            float inter = w * h;
            float uni = ia + ja[jj] - inter;

            float clx = fminf(ix0, jx0[jj]), cly = fminf(iy0, jy0[jj]);
            float crx = fmaxf(ix1, jx1[jj]), cry = fmaxf(iy1, jy1[jj]);
            float ac = (crx - clx) * (cry - cly);   // always >= 0

            float giou = __fdividef(inter, uni) - __fdividef(ac - uni, ac);
            float cls = __ldg(trow + jlab[jj]);
            float cost = 5.0f * l1 + 2.0f * cls - 2.0f * giou;
            r[jj] = jm[jj] ? cost : BIGV;
        }
        out4[((size_t)b * QQ + i) * (QQ / 4) + tid] =
            make_float4(r[0], r[1], r[2], r[3]);
    }
}

extern "C" void kernel_launch(void* const* d_in, const int* in_sizes, int n_in,
                              void* d_out, int out_size)
{
    const float*  pred_logits      = (const float*)d_in[0];
    const float4* pred_boxes       = (const float4*)d_in[1];
    const float*  pred_logits_base = (const float*)d_in[2];
    const float4* pred_boxes_base  = (const float4*)d_in[3];
    const float4* targets_boxes    = (const float4*)d_in[4];
    float* out = (float*)d_out;

    const long long c_elems = (long long)BB * QQ * QQ;
    int write_mask = (out_size >= c_elems + BB * QQ) ? 1 : 0;

    pseudo_kernel<<<(BB * QQ + 255) / 256, 256>>>(
        pred_logits_base, pred_boxes_base, targets_boxes,
        out + c_elems, write_mask);

    table_kernel<<<(BB * QQ * CCLS + 255) / 256, 256>>>(pred_logits);

    cost_kernel<<<dim3(ITILES, BB), TBLK>>>(pred_boxes, pred_boxes_base, out);
}

// round 2
// speedup vs baseline: 1.8402x; 1.8402x over previous
#include <cuda_runtime.h>

#define BB 32
#define QQ 900
#define CCLS 91
#define TT 30
#define BIGV 1e9f
#define ROWS_PER_BLK 8

// ---------------- device scratch (no allocations allowed) -------------------
__device__ int    g_cnt[BB];                 // survivors per batch
__device__ float4 g_cxyxy[BB * QQ];          // survivor base box xyxy
__device__ float4 g_cbox[BB * QQ];           // survivor base box cxcywh
__device__ int2   g_cmeta[BB * QQ];          // (j index, label)

// ---------------------------------------------------------------------------
// Kernel 0: zero counters
// ---------------------------------------------------------------------------
__global__ void init_kernel()
{
    if (threadIdx.x < BB) g_cnt[threadIdx.x] = 0;
}

// ---------------------------------------------------------------------------
// Kernel 1: warp-per-row pseudo labels + mask + survivor compaction.
// Mask GIoU path uses exact IEEE op order (__f*_rn, no FMA contraction):
// a mask flip swaps ~O(10) values for 1e9 across a whole output column.
// ---------------------------------------------------------------------------
__global__ void __launch_bounds__(256)
pseudo_kernel(const float* __restrict__ logits_base,
              const float4* __restrict__ boxes_base,
              const float4* __restrict__ targets,
              float* __restrict__ out_mask, int write_mask)
{
    int warp = (blockIdx.x * blockDim.x + threadIdx.x) >> 5;
    int lane = threadIdx.x & 31;
    if (warp >= BB * QQ) return;
    int b = warp / QQ;

    // ---- warp argmax over 91 logits (first-occurrence tie-break) ----
    const float* row = logits_base + (size_t)warp * CCLS;
    float best = -3.4e38f;
    int bi = 0;
    for (int c = lane; c < CCLS; c += 32) {
        float x = row[c];
        if (x > best) { best = x; bi = c; }          // increasing c -> keeps first
    }
#pragma unroll
    for (int off = 16; off > 0; off >>= 1) {
        float ov = __shfl_down_sync(0xFFFFFFFFu, best, off);
        int   oi = __shfl_down_sync(0xFFFFFFFFu, bi, off);
        if (ov > best || (ov == best && oi < bi)) { best = ov; bi = oi; }
    }
    best = __shfl_sync(0xFFFFFFFFu, best, 0);
    bi   = __shfl_sync(0xFFFFFFFFu, bi, 0);
    int keep = (best > 0.0f);                         // sigmoid(best) > 0.5

    // ---- base box -> xyxy (exact op order) ----
    float4 bb = boxes_base[warp];
    float bx0 = __fsub_rn(bb.x, __fmul_rn(0.5f, bb.z));
    float by0 = __fsub_rn(bb.y, __fmul_rn(0.5f, bb.w));
    float bx1 = __fadd_rn(bb.x, __fmul_rn(0.5f, bb.z));
    float by1 = __fadd_rn(bb.y, __fmul_rn(0.5f, bb.w));
    float barea = __fmul_rn(__fsub_rn(bx1, bx0), __fsub_rn(by1, by0));

    // ---- one target per lane, exact-order giou, ballot the violations ----
    int bad = 0;
    if (lane < TT) {
        float4 tb = targets[b * TT + lane];
        float tx0 = __fsub_rn(tb.x, __fmul_rn(0.5f, tb.z));
        float ty0 = __fsub_rn(tb.y, __fmul_rn(0.5f, tb.w));
        float tx1 = __fadd_rn(tb.x, __fmul_rn(0.5f, tb.z));
        float ty1 = __fadd_rn(tb.y, __fmul_rn(0.5f, tb.w));
        float tarea = __fmul_rn(__fsub_rn(tx1, tx0), __fsub_rn(ty1, ty0));

        float lx = fmaxf(bx0, tx0), ly = fmaxf(by0, ty0);
        float rx = fminf(bx1, tx1), ry = fminf(by1, ty1);
        float w = fmaxf(__fsub_rn(rx, lx), 0.0f);
        float h = fmaxf(__fsub_rn(ry, ly), 0.0f);
        float inter = __fmul_rn(w, h);
        float uni = __fsub_rn(__fadd_rn(barea, tarea), inter);
        float iou = __fdiv_rn(inter, uni);

        float clx = fminf(bx0, tx0), cly = fminf(by0, ty0);
        float crx = fmaxf(bx1, tx1), cry = fmaxf(by1, ty1);
        float cw = fmaxf(__fsub_rn(crx, clx), 0.0f);
        float ch = fmaxf(__fsub_rn(cry, cly), 0.0f);
        float ac = __fmul_rn(cw, ch);
        float g = __fsub_rn(iou, __fdiv_rn(__fsub_rn(ac, uni), ac));
        bad = !(-g > -0.1f);                          // reference: all(-giou > -0.1)
    }
    keep = keep && (__ballot_sync(0xFFFFFFFFu, bad) == 0u);

    if (lane == 0) {
        if (write_mask) out_mask[warp] = keep ? 1.0f : 0.0f;
        if (keep) {
            int s = atomicAdd(&g_cnt[b], 1);
            int q = warp - b * QQ;
            g_cxyxy[b * QQ + s] = make_float4(bx0, by0, bx1, by1);
            g_cbox[b * QQ + s]  = bb;
            g_cmeta[b * QQ + s] = make_int2(q, bi);
        }
    }
}

// ---------------------------------------------------------------------------
// Kernel 2: one warp per output row (b,i). Fill SMEM row with BIG, compute
// cost only for the n_b compacted survivors (scatter into SMEM), stream the
// row out with coalesced float4 stores. Class focal cost computed on the fly
// at the survivor's label (beats a full [B,Q,C] table when n_b << 900).
// ---------------------------------------------------------------------------
__global__ void __launch_bounds__(ROWS_PER_BLK * 32)
rows_kernel(const float4* __restrict__ pred_boxes,
            const float*  __restrict__ pred_logits,
            float* __restrict__ out)
{
    __shared__ float srow[ROWS_PER_BLK][QQ];

    int wi   = threadIdx.x >> 5;
    int lane = threadIdx.x & 31;
    int row  = blockIdx.x * ROWS_PER_BLK + wi;        // 28800 rows, grid = 3600 exact
    int b = row / QQ;
    int nb = g_cnt[b];

    // pred box i (broadcast load) -> xyxy + area
    float4 pb = __ldg(&pred_boxes[row]);
    float hw = 0.5f * pb.z, hh = 0.5f * pb.w;
    float ix0 = pb.x - hw, iy0 = pb.y - hh;
    float ix1 = pb.x + hw, iy1 = pb.y + hh;
    float ia  = (ix1 - ix0) * (iy1 - iy0);
    const float* lrow = pred_logits + (size_t)row * CCLS;

    // fill row buffer with BIG
    float4* s4 = (float4*)srow[wi];
#pragma unroll
    for (int t = lane; t < QQ / 4; t += 32)
        s4[t] = make_float4(BIGV, BIGV, BIGV, BIGV);
    __syncwarp();

    // survivors (tiny, L1-resident compact arrays)
    for (int s = lane; s < nb; s += 32) {
        float4 jx = __ldg(&g_cxyxy[b * QQ + s]);      // x0 y0 x1 y1
        float4 jb = __ldg(&g_cbox[b * QQ + s]);       // cx cy w h
        int2   jm = __ldg(&g_cmeta[b * QQ + s]);      // (j, label)

        float l1 = fabsf(pb.x - jb.x) + fabsf(pb.y - jb.y)
                 + fabsf(pb.z - jb.z) + fabsf(pb.w - jb.w);

        float ja = (jx.z - jx.x) * (jx.w - jx.y);
        float lx = fmaxf(ix0, jx.x), ly = fmaxf(iy0, jx.y);
        float rx = fminf(ix1, jx.z), ry = fminf(iy1, jx.w);
        float w = fmaxf(rx - lx, 0.0f);
        float h = fmaxf(ry - ly, 0.0f);
        float inter = w * h;
        float uni = ia + ja - inter;

        float clx = fminf(ix0, jx.x), cly = fminf(iy0, jx.y);
        float crx = fmaxf(ix1, jx.z), cry = fmaxf(iy1, jx.w);
        float ac = (crx - clx) * (cry - cly);

        float giou = __fdividef(inter, uni) - __fdividef(ac - uni, ac);

        // focal class cost at this survivor's label
        float x = __ldg(lrow + jm.y);
        float p = 1.0f / (1.0f + expf(-x));
        float omp = 1.0f - p;
        float cls = 0.25f * omp * omp * (-logf(p + 1e-8f))
                  - 0.75f * p * p * (-logf(omp + 1e-8f));

        srow[wi][jm.x] = 5.0f * l1 + 2.0f * cls - 2.0f * giou;
    }
    __syncwarp();

    // coalesced stream-out
    float4* o4 = (float4*)(out + (size_t)row * QQ);
#pragma unroll
    for (int t = lane; t < QQ / 4; t += 32)
        o4[t] = s4[t];
}

extern "C" void kernel_launch(void* const* d_in, const int* in_sizes, int n_in,
                              void* d_out, int out_size)
{
    const float*  pred_logits      = (const float*)d_in[0];
    const float4* pred_boxes       = (const float4*)d_in[1];
    const float*  pred_logits_base = (const float*)d_in[2];
    const float4* pred_boxes_base  = (const float4*)d_in[3];
    const float4* targets_boxes    = (const float4*)d_in[4];
    float* out = (float*)d_out;

    const long long c_elems = (long long)BB * QQ * QQ;
    int write_mask = (out_size >= c_elems + BB * QQ) ? 1 : 0;

    init_kernel<<<1, 32>>>();

    // 28800 warps, 8 warps/block -> 3600 blocks
    pseudo_kernel<<<(BB * QQ) / ROWS_PER_BLK, ROWS_PER_BLK * 32>>>(
        pred_logits_base, pred_boxes_base, targets_boxes,
        out + c_elems, write_mask);

    rows_kernel<<<(BB * QQ) / ROWS_PER_BLK, ROWS_PER_BLK * 32>>>(
        pred_boxes, pred_logits, out);
}

// round 3
// speedup vs baseline: 1.9682x; 1.0695x over previous
#include <cuda_runtime.h>
#include <cstdint>

#define BB 32
#define QQ 900
#define CCLS 91
#define TT 30
#define BIGV 1e9f
#define RPB 8                      // rows per block in rows_kernel
#define IBLK ((QQ + RPB - 1) / RPB) // 113

// per-row packed pseudo info: keep ? label : -1
__device__ int g_lk[BB * QQ];

// ---------------------------------------------------------------------------
// Kernel 1: warp-per-row pseudo labels + mask.
// Mask GIoU path uses exact IEEE op order (__f*_rn, no FMA contraction):
// a mask flip swaps ~O(10) values for 1e9 across a whole output column.
// ---------------------------------------------------------------------------
__global__ void __launch_bounds__(256)
pseudo_kernel(const float* __restrict__ logits_base,
              const float4* __restrict__ boxes_base,
              const float4* __restrict__ targets,
              float* __restrict__ out_mask, int write_mask)
{
    int warp = (blockIdx.x * blockDim.x + threadIdx.x) >> 5;
    int lane = threadIdx.x & 31;
    if (warp >= BB * QQ) return;
    int b = warp / QQ;

    // warp argmax over 91 logits (first-occurrence tie-break)
    const float* row = logits_base + (size_t)warp * CCLS;
    float best = -3.4e38f;
    int bi = 0;
    for (int c = lane; c < CCLS; c += 32) {
        float x = row[c];
        if (x > best) { best = x; bi = c; }
    }
#pragma unroll
    for (int off = 16; off > 0; off >>= 1) {
        float ov = __shfl_down_sync(0xFFFFFFFFu, best, off);
        int   oi = __shfl_down_sync(0xFFFFFFFFu, bi, off);
        if (ov > best || (ov == best && oi < bi)) { best = ov; bi = oi; }
    }
    best = __shfl_sync(0xFFFFFFFFu, best, 0);
    bi   = __shfl_sync(0xFFFFFFFFu, bi, 0);
    int keep = (best > 0.0f);                 // sigmoid(best) > 0.5

    // base box -> xyxy, exact IEEE op order
    float4 bb = boxes_base[warp];
    float bx0 = __fsub_rn(bb.x, __fmul_rn(0.5f, bb.z));
    float by0 = __fsub_rn(bb.y, __fmul_rn(0.5f, bb.w));
    float bx1 = __fadd_rn(bb.x, __fmul_rn(0.5f, bb.z));
    float by1 = __fadd_rn(bb.y, __fmul_rn(0.5f, bb.w));
    float barea = __fmul_rn(__fsub_rn(bx1, bx0), __fsub_rn(by1, by0));

    int bad = 0;
    if (lane < TT) {
        float4 tb = targets[b * TT + lane];
        float tx0 = __fsub_rn(tb.x, __fmul_rn(0.5f, tb.z));
        float ty0 = __fsub_rn(tb.y, __fmul_rn(0.5f, tb.w));
        float tx1 = __fadd_rn(tb.x, __fmul_rn(0.5f, tb.z));
        float ty1 = __fadd_rn(tb.y, __fmul_rn(0.5f, tb.w));
        float tarea = __fmul_rn(__fsub_rn(tx1, tx0), __fsub_rn(ty1, ty0));

        float lx = fmaxf(bx0, tx0), ly = fmaxf(by0, ty0);
        float rx = fminf(bx1, tx1), ry = fminf(by1, ty1);
        float w = fmaxf(__fsub_rn(rx, lx), 0.0f);
        float h = fmaxf(__fsub_rn(ry, ly), 0.0f);
        float inter = __fmul_rn(w, h);
        float uni = __fsub_rn(__fadd_rn(barea, tarea), inter);
        float iou = __fdiv_rn(inter, uni);

        float clx = fminf(bx0, tx0), cly = fminf(by0, ty0);
        float crx = fmaxf(bx1, tx1), cry = fmaxf(by1, ty1);
        float cw = fmaxf(__fsub_rn(crx, clx), 0.0f);
        float ch = fmaxf(__fsub_rn(cry, cly), 0.0f);
        float ac = __fmul_rn(cw, ch);
        float g = __fsub_rn(iou, __fdiv_rn(__fsub_rn(ac, uni), ac));
        bad = !(-g > -0.1f);
    }
    keep = keep && (__ballot_sync(0xFFFFFFFFu, bad) == 0u);

    if (lane == 0) {
        g_lk[warp] = keep ? bi : -1;
        if (write_mask) out_mask[warp] = keep ? 1.0f : 0.0f;
    }
}

// ---------------------------------------------------------------------------
// Kernel 2: rows. Block = 8 rows of batch b. Per-block survivor compaction
// from g_lk (flags L2-hot), row staged in SMEM (BIG fill + sparse scatter),
// streamed out via cp.async.bulk (TMA) — no LDS/STG round-trip.
// ---------------------------------------------------------------------------
__global__ void __launch_bounds__(RPB * 32)
rows_kernel(const float4* __restrict__ pred_boxes,
            const float*  __restrict__ pred_logits,
            const float4* __restrict__ boxes_base,
            float* __restrict__ out)
{
    __shared__ float srow[RPB][QQ];
    __shared__ int   s_jl[QQ];       // packed (label<<16 | j) survivors
    __shared__ int   s_cnt;

    int b = blockIdx.y;
    int tid = threadIdx.x;

    if (tid == 0) s_cnt = 0;
    __syncthreads();

    // batch-wide survivor compaction (order-free; output independent of order)
    for (int j = tid; j < QQ; j += RPB * 32) {
        int lk = __ldg(&g_lk[b * QQ + j]);
        if (lk >= 0) {
            int p = atomicAdd(&s_cnt, 1);
            s_jl[p] = j | (lk << 16);
        }
    }
    __syncthreads();
    int nb = s_cnt;

    int wi = tid >> 5;
    int lane = tid & 31;
    int i = blockIdx.x * RPB + wi;
    uint32_t saddr;
    {
        void* p = (void*)srow[wi];
        asm("{ .reg .u64 t; cvta.to.shared.u64 t, %1; cvt.u32.u64 %0, t; }"
            : "=r"(saddr) : "l"(p));
    }

    if (i < QQ) {
        int rowi = b * QQ + i;
        float4 pb = __ldg(&pred_boxes[rowi]);
        float hw = 0.5f * pb.z, hh = 0.5f * pb.w;
        float ix0 = pb.x - hw, iy0 = pb.y - hh;
        float ix1 = pb.x + hw, iy1 = pb.y + hh;
        float ia  = (ix1 - ix0) * (iy1 - iy0);
        const float* lrow = pred_logits + (size_t)rowi * CCLS;

        // BIG fill
        float4* s4 = (float4*)srow[wi];
#pragma unroll
        for (int t = lane; t < QQ / 4; t += 32)
            s4[t] = make_float4(BIGV, BIGV, BIGV, BIGV);
        __syncwarp();

        // survivor costs
        for (int s = lane; s < nb; s += 32) {
            int jl = s_jl[s];
            int j = jl & 0xFFFF;
            int lab = jl >> 16;
            float4 jb = __ldg(&boxes_base[b * QQ + j]);

            float l1 = fabsf(pb.x - jb.x) + fabsf(pb.y - jb.y)
                     + fabsf(pb.z - jb.z) + fabsf(pb.w - jb.w);

            float jhw = 0.5f * jb.z, jhh = 0.5f * jb.w;
            float jx0 = jb.x - jhw, jy0 = jb.y - jhh;
            float jx1 = jb.x + jhw, jy1 = jb.y + jhh;
            float ja  = (jx1 - jx0) * (jy1 - jy0);

            float lx = fmaxf(ix0, jx0), ly = fmaxf(iy0, jy0);
            float rx = fminf(ix1, jx1), ry = fminf(iy1, jy1);
            float w = fmaxf(rx - lx, 0.0f);
            float h = fmaxf(ry - ly, 0.0f);
            float inter = w * h;
            float uni = ia + ja - inter;

            float clx = fminf(ix0, jx0), cly = fminf(iy0, jy0);
            float crx = fmaxf(ix1, jx1), cry = fmaxf(iy1, jy1);
            float ac = (crx - clx) * (cry - cly);

            float giou = __fdividef(inter, uni) - __fdividef(ac - uni, ac);

            float x = __ldg(lrow + lab);
            float p = 1.0f / (1.0f + expf(-x));
            float omp = 1.0f - p;
            float cls = 0.25f * omp * omp * (-logf(p + 1e-8f))
                      - 0.75f * p * p * (-logf(omp + 1e-8f));

            srow[wi][j] = 5.0f * l1 + 2.0f * cls - 2.0f * giou;
        }
        __syncwarp();
        asm volatile("fence.proxy.async.shared::cta;" ::: "memory");

        if (lane == 0) {
            const float* gdst = out + (size_t)rowi * QQ;
            asm volatile(
                "cp.async.bulk.global.shared::cta.bulk_group [%0], [%1], %2;"
                :: "l"(gdst), "r"(saddr), "r"((int)(QQ * 4)) : "memory");
            asm volatile("cp.async.bulk.commit_group;" ::: "memory");
        }
    }

    // keep SMEM alive until TMA reads complete
    if (lane == 0 && i < QQ)
        asm volatile("cp.async.bulk.wait_group.read 0;" ::: "memory");
}

extern "C" void kernel_launch(void* const* d_in, const int* in_sizes, int n_in,
                              void* d_out, int out_size)
{
    const float*  pred_logits      = (const float*)d_in[0];
    const float4* pred_boxes       = (const float4*)d_in[1];
    const float*  pred_logits_base = (const float*)d_in[2];
    const float4* pred_boxes_base  = (const float4*)d_in[3];
    const float4* targets_boxes    = (const float4*)d_in[4];
    float* out = (float*)d_out;

    const long long c_elems = (long long)BB * QQ * QQ;
    int write_mask = (out_size >= c_elems + BB * QQ) ? 1 : 0;

    pseudo_kernel<<<(BB * QQ) / RPB, RPB * 32>>>(
        pred_logits_base, pred_boxes_base, targets_boxes,
        out + c_elems, write_mask);

    rows_kernel<<<dim3(IBLK, BB), RPB * 32>>>(
        pred_boxes, pred_logits, pred_boxes_base, out);
}

// round 4
// speedup vs baseline: 2.1941x; 1.1148x over previous
#include <cuda_runtime.h>
#include <cstdint>

#define BB 32
#define QQ 900
#define CCLS 91
#define TT 30
#define BIGV 1e9f
#define RPB 8
#define IBLK ((QQ + RPB - 1) / RPB)   // 113

// per-row packed pseudo info: keep ? label : -1
__device__ int g_lk[BB * QQ];

// ---------------------------------------------------------------------------
// Kernel 1: warp-per-row pseudo labels + mask.
// Mask GIoU path uses exact IEEE op order (__f*_rn, no FMA contraction):
// a mask flip swaps ~O(10) values for 1e9 across a whole output column.
// ---------------------------------------------------------------------------
__global__ void __launch_bounds__(256)
pseudo_kernel(const float* __restrict__ logits_base,
              const float4* __restrict__ boxes_base,
              const float4* __restrict__ targets,
              float* __restrict__ out_mask, int write_mask)
{
    int warp = (blockIdx.x * blockDim.x + threadIdx.x) >> 5;
    int lane = threadIdx.x & 31;
    if (warp >= BB * QQ) return;
    int b = warp / QQ;

    // warp argmax over 91 logits (first-occurrence tie-break)
    const float* row = logits_base + (size_t)warp * CCLS;
    float best = -3.4e38f;
    int bi = 0;
    for (int c = lane; c < CCLS; c += 32) {
        float x = row[c];
        if (x > best) { best = x; bi = c; }
    }
#pragma unroll
    for (int off = 16; off > 0; off >>= 1) {
        float ov = __shfl_down_sync(0xFFFFFFFFu, best, off);
        int   oi = __shfl_down_sync(0xFFFFFFFFu, bi, off);
        if (ov > best || (ov == best && oi < bi)) { best = ov; bi = oi; }
    }
    best = __shfl_sync(0xFFFFFFFFu, best, 0);
    bi   = __shfl_sync(0xFFFFFFFFu, bi, 0);
    int keep = (best > 0.0f);                 // sigmoid(best) > 0.5

    float4 bb = boxes_base[warp];
    float bx0 = __fsub_rn(bb.x, __fmul_rn(0.5f, bb.z));
    float by0 = __fsub_rn(bb.y, __fmul_rn(0.5f, bb.w));
    float bx1 = __fadd_rn(bb.x, __fmul_rn(0.5f, bb.z));
    float by1 = __fadd_rn(bb.y, __fmul_rn(0.5f, bb.w));
    float barea = __fmul_rn(__fsub_rn(bx1, bx0), __fsub_rn(by1, by0));

    int bad = 0;
    if (lane < TT) {
        float4 tb = targets[b * TT + lane];
        float tx0 = __fsub_rn(tb.x, __fmul_rn(0.5f, tb.z));
        float ty0 = __fsub_rn(tb.y, __fmul_rn(0.5f, tb.w));
        float tx1 = __fadd_rn(tb.x, __fmul_rn(0.5f, tb.z));
        float ty1 = __fadd_rn(tb.y, __fmul_rn(0.5f, tb.w));
        float tarea = __fmul_rn(__fsub_rn(tx1, tx0), __fsub_rn(ty1, ty0));

        float lx = fmaxf(bx0, tx0), ly = fmaxf(by0, ty0);
        float rx = fminf(bx1, tx1), ry = fminf(by1, ty1);
        float w = fmaxf(__fsub_rn(rx, lx), 0.0f);
        float h = fmaxf(__fsub_rn(ry, ly), 0.0f);
        float inter = __fmul_rn(w, h);
        float uni = __fsub_rn(__fadd_rn(barea, tarea), inter);
        float iou = __fdiv_rn(inter, uni);

        float clx = fminf(bx0, tx0), cly = fminf(by0, ty0);
        float crx = fmaxf(bx1, tx1), cry = fmaxf(by1, ty1);
        float cw = fmaxf(__fsub_rn(crx, clx), 0.0f);
        float ch = fmaxf(__fsub_rn(cry, cly), 0.0f);
        float ac = __fmul_rn(cw, ch);
        float g = __fsub_rn(iou, __fdiv_rn(__fsub_rn(ac, uni), ac));
        bad = !(-g > -0.1f);
    }
    keep = keep && (__ballot_sync(0xFFFFFFFFu, bad) == 0u);

    if (lane == 0) {
        g_lk[warp] = keep ? bi : -1;
        if (write_mask) out_mask[warp] = keep ? 1.0f : 0.0f;
    }
}

// ---------------------------------------------------------------------------
// Kernel 2: rows. Block = 8 rows. Per-block focal LUT (8x91, fast-math),
// per-block survivor compaction, lane-owns-survivor / inner-loop-over-rows,
// SMEM row staging streamed out via cp.async.bulk.
// ---------------------------------------------------------------------------
__global__ void __launch_bounds__(RPB * 32)
rows_kernel(const float4* __restrict__ pred_boxes,
            const float*  __restrict__ pred_logits,
            const float4* __restrict__ boxes_base,
            float* __restrict__ out)
{
    __shared__ __align__(16) float srow[RPB][QQ];
    __shared__ float4 s_rb[RPB];        // row box cxcywh
    __shared__ float4 s_rx[RPB];        // row box xyxy
    __shared__ float  s_ra[RPB];        // row box area
    __shared__ float  s_cls[RPB][CCLS]; // focal class cost LUT
    __shared__ int    s_jl[QQ];
    __shared__ int    s_cnt;

    int b = blockIdx.y;
    int i0 = blockIdx.x * RPB;
    int nrows = min(RPB, QQ - i0);
    int tid = threadIdx.x;
    int wi = tid >> 5, lane = tid & 31;

    if (tid == 0) s_cnt = 0;
    if (tid < nrows) {
        float4 pb = __ldg(&pred_boxes[b * QQ + i0 + tid]);
        float hw = 0.5f * pb.z, hh = 0.5f * pb.w;
        float x0 = pb.x - hw, y0 = pb.y - hh;
        float x1 = pb.x + hw, y1 = pb.y + hh;
        s_rb[tid] = pb;
        s_rx[tid] = make_float4(x0, y0, x1, y1);
        s_ra[tid] = (x1 - x0) * (y1 - y0);
    }
    __syncthreads();

    // focal class-cost LUT: 8 rows x 91 labels, fast-math
    for (int idx = tid; idx < nrows * CCLS; idx += RPB * 32) {
        int r = idx / CCLS, c = idx - r * CCLS;
        float x = __ldg(&pred_logits[(size_t)(b * QQ + i0 + r) * CCLS + c]);
        float e = __expf(-x);
        float p = __fdividef(1.0f, 1.0f + e);
        float omp = 1.0f - p;
        s_cls[r][c] = 0.25f * omp * omp * (-__logf(p + 1e-8f))
                    - 0.75f * p * p * (-__logf(omp + 1e-8f));
    }

    // survivor compaction (order-free)
    for (int j = tid; j < QQ; j += RPB * 32) {
        int lk = __ldg(&g_lk[b * QQ + j]);
        if (lk >= 0) {
            int p = atomicAdd(&s_cnt, 1);
            s_jl[p] = j | (lk << 16);
        }
    }

    // BIG fill (all 8 rows, all 256 threads)
    {
        float4* s4 = (float4*)srow;
        const int n4 = RPB * QQ / 4;   // 1800
        for (int t = tid; t < n4; t += RPB * 32)
            s4[t] = make_float4(BIGV, BIGV, BIGV, BIGV);
    }
    __syncthreads();
    int nb = s_cnt;

    // pair loop: lane owns one survivor, inner loop over the block's rows
    for (int s0 = wi * 32; s0 < nb; s0 += RPB * 32) {
        int s = s0 + lane;
        if (s < nb) {
            int jl = s_jl[s];
            int j = jl & 0xFFFF;
            int lab = jl >> 16;
            float4 jb = __ldg(&boxes_base[b * QQ + j]);
            float jhw = 0.5f * jb.z, jhh = 0.5f * jb.w;
            float jx0 = jb.x - jhw, jy0 = jb.y - jhh;
            float jx1 = jb.x + jhw, jy1 = jb.y + jhh;
            float ja  = (jx1 - jx0) * (jy1 - jy0);

#pragma unroll
            for (int r = 0; r < RPB; r++) {
                if (r < nrows) {
                    float4 pb = s_rb[r];
                    float4 px = s_rx[r];
                    float ia = s_ra[r];

                    float l1 = fabsf(pb.x - jb.x) + fabsf(pb.y - jb.y)
                             + fabsf(pb.z - jb.z) + fabsf(pb.w - jb.w);

                    float lx = fmaxf(px.x, jx0), ly = fmaxf(px.y, jy0);
                    float rx = fminf(px.z, jx1), ry = fminf(px.w, jy1);
                    float w = fmaxf(rx - lx, 0.0f);
                    float h = fmaxf(ry - ly, 0.0f);
                    float inter = w * h;
                    float uni = ia + ja - inter;

                    float clx = fminf(px.x, jx0), cly = fminf(px.y, jy0);
                    float crx = fmaxf(px.z, jx1), cry = fmaxf(px.w, jy1);
                    float ac = (crx - clx) * (cry - cly);

                    float giou = __fdividef(inter, uni)
                               - __fdividef(ac - uni, ac);
                    float cls = s_cls[r][lab];

                    srow[r][j] = 5.0f * l1 + 2.0f * cls - 2.0f * giou;
                }
            }
        }
    }
    __syncthreads();
    asm volatile("fence.proxy.async.shared::cta;" ::: "memory");

    if (tid == 0) {
        for (int r = 0; r < nrows; r++) {
            const float* gdst = out + (size_t)(b * QQ + i0 + r) * QQ;
            uint32_t saddr;
            void* p = (void*)srow[r];
            asm("{ .reg .u64 t; cvta.to.shared.u64 t, %1; cvt.u32.u64 %0, t; }"
                : "=r"(saddr) : "l"(p));
            asm volatile(
                "cp.async.bulk.global.shared::cta.bulk_group [%0], [%1], %2;"
                :: "l"(gdst), "r"(saddr), "r"((int)(QQ * 4)) : "memory");
        }
        asm volatile("cp.async.bulk.commit_group;" ::: "memory");
        asm volatile("cp.async.bulk.wait_group.read 0;" ::: "memory");
    }
}

extern "C" void kernel_launch(void* const* d_in, const int* in_sizes, int n_in,
                              void* d_out, int out_size)
{
    const float*  pred_logits      = (const float*)d_in[0];
    const float4* pred_boxes       = (const float4*)d_in[1];
    const float*  pred_logits_base = (const float*)d_in[2];
    const float4* pred_boxes_base  = (const float4*)d_in[3];
    const float4* targets_boxes    = (const float4*)d_in[4];
    float* out = (float*)d_out;

    const long long c_elems = (long long)BB * QQ * QQ;
    int write_mask = (out_size >= c_elems + BB * QQ) ? 1 : 0;

    pseudo_kernel<<<(BB * QQ) / RPB, RPB * 32>>>(
        pred_logits_base, pred_boxes_base, targets_boxes,
        out + c_elems, write_mask);

    rows_kernel<<<dim3(IBLK, BB), RPB * 32>>>(
        pred_boxes, pred_logits, pred_boxes_base, out);
}

// round 5
// speedup vs baseline: 2.1954x; 1.0006x over previous
#include <cuda_runtime.h>
#include <cstdint>

#define BB 32
#define QQ 900
#define CCLS 91
#define TT 30
#define BIGV 1e9f
#define RPB 8
#define IBLK ((QQ + RPB - 1) / RPB)   // 113

// per-row packed pseudo info: keep ? label : -1
__device__ int g_lk[BB * QQ];

// ---------------------------------------------------------------------------
// Kernel 1: warp-per-row pseudo labels + mask.
// Mask GIoU path uses exact IEEE op order (__f*_rn, no FMA contraction):
// a mask flip swaps ~O(10) values for 1e9 across a whole output column.
// ---------------------------------------------------------------------------
__global__ void __launch_bounds__(256)
pseudo_kernel(const float* __restrict__ logits_base,
              const float4* __restrict__ boxes_base,
              const float4* __restrict__ targets,
              float* __restrict__ out_mask, int write_mask)
{
    int warp = (blockIdx.x * blockDim.x + threadIdx.x) >> 5;
    int lane = threadIdx.x & 31;
    if (warp >= BB * QQ) return;
    int b = warp / QQ;

    // warp argmax over 91 logits (first-occurrence tie-break)
    const float* row = logits_base + (size_t)warp * CCLS;
    float best = -3.4e38f;
    int bi = 0;
    for (int c = lane; c < CCLS; c += 32) {
        float x = row[c];
        if (x > best) { best = x; bi = c; }
    }
#pragma unroll
    for (int off = 16; off > 0; off >>= 1) {
        float ov = __shfl_down_sync(0xFFFFFFFFu, best, off);
        int   oi = __shfl_down_sync(0xFFFFFFFFu, bi, off);
        if (ov > best || (ov == best && oi < bi)) { best = ov; bi = oi; }
    }
    best = __shfl_sync(0xFFFFFFFFu, best, 0);
    bi   = __shfl_sync(0xFFFFFFFFu, bi, 0);
    int keep = (best > 0.0f);                 // sigmoid(best) > 0.5

    float4 bb = boxes_base[warp];
    float bx0 = __fsub_rn(bb.x, __fmul_rn(0.5f, bb.z));
    float by0 = __fsub_rn(bb.y, __fmul_rn(0.5f, bb.w));
    float bx1 = __fadd_rn(bb.x, __fmul_rn(0.5f, bb.z));
    float by1 = __fadd_rn(bb.y, __fmul_rn(0.5f, bb.w));
    float barea = __fmul_rn(__fsub_rn(bx1, bx0), __fsub_rn(by1, by0));

    int bad = 0;
    if (lane < TT) {
        float4 tb = targets[b * TT + lane];
        float tx0 = __fsub_rn(tb.x, __fmul_rn(0.5f, tb.z));
        float ty0 = __fsub_rn(tb.y, __fmul_rn(0.5f, tb.w));
        float tx1 = __fadd_rn(tb.x, __fmul_rn(0.5f, tb.z));
        float ty1 = __fadd_rn(tb.y, __fmul_rn(0.5f, tb.w));
        float tarea = __fmul_rn(__fsub_rn(tx1, tx0), __fsub_rn(ty1, ty0));

        float lx = fmaxf(bx0, tx0), ly = fmaxf(by0, ty0);
        float rx = fminf(bx1, tx1), ry = fminf(by1, ty1);
        float w = fmaxf(__fsub_rn(rx, lx), 0.0f);
        float h = fmaxf(__fsub_rn(ry, ly), 0.0f);
        float inter = __fmul_rn(w, h);
        float uni = __fsub_rn(__fadd_rn(barea, tarea), inter);
        float iou = __fdiv_rn(inter, uni);

        float clx = fminf(bx0, tx0), cly = fminf(by0, ty0);
        float crx = fmaxf(bx1, tx1), cry = fmaxf(by1, ty1);
        float cw = fmaxf(__fsub_rn(crx, clx), 0.0f);
        float ch = fmaxf(__fsub_rn(cry, cly), 0.0f);
        float ac = __fmul_rn(cw, ch);
        float g = __fsub_rn(iou, __fdiv_rn(__fsub_rn(ac, uni), ac));
        bad = !(-g > -0.1f);
    }
    keep = keep && (__ballot_sync(0xFFFFFFFFu, bad) == 0u);

    if (lane == 0) {
        g_lk[warp] = keep ? bi : -1;
        if (write_mask) out_mask[warp] = keep ? 1.0f : 0.0f;
    }
}

// ---------------------------------------------------------------------------
// Kernel 2: rows. Block = 8 rows. Survivor compaction FIRST (marks used
// labels), then focal LUT computed ONLY for used labels (MUFU cut ~3x),
// lane-owns-survivor pair loop, SMEM staging streamed out via cp.async.bulk.
// ---------------------------------------------------------------------------
__global__ void __launch_bounds__(RPB * 32)
rows_kernel(const float4* __restrict__ pred_boxes,
            const float*  __restrict__ pred_logits,
            const float4* __restrict__ boxes_base,
            float* __restrict__ out)
{
    __shared__ __align__(16) float srow[RPB][QQ];
    __shared__ float4 s_rb[RPB];        // row box cxcywh
    __shared__ float4 s_rx[RPB];        // row box xyxy
    __shared__ float  s_ra[RPB];        // row box area
    __shared__ float  s_cls[RPB][CCLS]; // focal class cost LUT (used labels only)
    __shared__ int    s_used[CCLS];
    __shared__ int    s_jl[QQ];
    __shared__ int    s_cnt;

    int b = blockIdx.y;
    int i0 = blockIdx.x * RPB;
    int nrows = min(RPB, QQ - i0);
    int tid = threadIdx.x;
    int wi = tid >> 5, lane = tid & 31;

    if (tid == 0) s_cnt = 0;
    if (tid < CCLS) s_used[tid] = 0;
    if (tid >= 128 && tid - 128 < nrows) {
        int r = tid - 128;
        float4 pb = __ldg(&pred_boxes[b * QQ + i0 + r]);
        float hw = 0.5f * pb.z, hh = 0.5f * pb.w;
        float x0 = pb.x - hw, y0 = pb.y - hh;
        float x1 = pb.x + hw, y1 = pb.y + hh;
        s_rb[r] = pb;
        s_rx[r] = make_float4(x0, y0, x1, y1);
        s_ra[r] = (x1 - x0) * (y1 - y0);
    }
    __syncthreads();

    // survivor compaction + used-label marking (order-free)
    for (int j = tid; j < QQ; j += RPB * 32) {
        int lk = __ldg(&g_lk[b * QQ + j]);
        if (lk >= 0) {
            int p = atomicAdd(&s_cnt, 1);
            s_jl[p] = j | (lk << 16);
            s_used[lk] = 1;
        }
    }
    __syncthreads();
    int nb = s_cnt;

    // focal class-cost LUT: only for labels that actually appear
    for (int idx = tid; idx < nrows * CCLS; idx += RPB * 32) {
        int r = idx / CCLS, c = idx - r * CCLS;
        if (s_used[c]) {
            float x = __ldg(&pred_logits[(size_t)(b * QQ + i0 + r) * CCLS + c]);
            float e = __expf(-x);
            float p = __fdividef(1.0f, 1.0f + e);
            float omp = 1.0f - p;
            s_cls[r][c] = 0.25f * omp * omp * (-__logf(p + 1e-8f))
                        - 0.75f * p * p * (-__logf(omp + 1e-8f));
        }
    }

    // BIG fill (all rows, all threads)
    {
        float4* s4 = (float4*)srow;
        const int n4 = RPB * QQ / 4;   // 1800
        for (int t = tid; t < n4; t += RPB * 32)
            s4[t] = make_float4(BIGV, BIGV, BIGV, BIGV);
    }
    __syncthreads();

    // pair loop: lane owns one survivor, inner loop over the block's rows
    for (int s0 = wi * 32; s0 < nb; s0 += RPB * 32) {
        int s = s0 + lane;
        if (s < nb) {
            int jl = s_jl[s];
            int j = jl & 0xFFFF;
            int lab = jl >> 16;
            float4 jb = __ldg(&boxes_base[b * QQ + j]);
            float jhw = 0.5f * jb.z, jhh = 0.5f * jb.w;
            float jx0 = jb.x - jhw, jy0 = jb.y - jhh;
            float jx1 = jb.x + jhw, jy1 = jb.y + jhh;
            float ja  = (jx1 - jx0) * (jy1 - jy0);

#pragma unroll
            for (int r = 0; r < RPB; r++) {
                if (r < nrows) {
                    float4 pb = s_rb[r];
                    float4 px = s_rx[r];
                    float ia = s_ra[r];

                    float l1 = fabsf(pb.x - jb.x) + fabsf(pb.y - jb.y)
                             + fabsf(pb.z - jb.z) + fabsf(pb.w - jb.w);

                    float lx = fmaxf(px.x, jx0), ly = fmaxf(px.y, jy0);
                    float rx = fminf(px.z, jx1), ry = fminf(px.w, jy1);
                    float w = fmaxf(rx - lx, 0.0f);
                    float h = fmaxf(ry - ly, 0.0f);
                    float inter = w * h;
                    float uni = ia + ja - inter;

                    float clx = fminf(px.x, jx0), cly = fminf(px.y, jy0);
                    float crx = fmaxf(px.z, jx1), cry = fmaxf(px.w, jy1);
                    float ac = (crx - clx) * (cry - cly);

                    float giou = __fdividef(inter, uni)
                               - __fdividef(ac - uni, ac);
                    float cls = s_cls[r][lab];

                    srow[r][j] = 5.0f * l1 + 2.0f * cls - 2.0f * giou;
                }
            }
        }
    }
    __syncthreads();
    asm volatile("fence.proxy.async.shared::cta;" ::: "memory");

    if (tid == 0) {
        for (int r = 0; r < nrows; r++) {
            const float* gdst = out + (size_t)(b * QQ + i0 + r) * QQ;
            uint32_t saddr;
            void* p = (void*)srow[r];
            asm("{ .reg .u64 t; cvta.to.shared.u64 t, %1; cvt.u32.u64 %0, t; }"
                : "=r"(saddr) : "l"(p));
            asm volatile(
                "cp.async.bulk.global.shared::cta.bulk_group [%0], [%1], %2;"
                :: "l"(gdst), "r"(saddr), "r"((int)(QQ * 4)) : "memory");
        }
        asm volatile("cp.async.bulk.commit_group;" ::: "memory");
        asm volatile("cp.async.bulk.wait_group.read 0;" ::: "memory");
    }
}

extern "C" void kernel_launch(void* const* d_in, const int* in_sizes, int n_in,
                              void* d_out, int out_size)
{
    const float*  pred_logits      = (const float*)d_in[0];
    const float4* pred_boxes       = (const float4*)d_in[1];
    const float*  pred_logits_base = (const float*)d_in[2];
    const float4* pred_boxes_base  = (const float4*)d_in[3];
    const float4* targets_boxes    = (const float4*)d_in[4];
    float* out = (float*)d_out;

    const long long c_elems = (long long)BB * QQ * QQ;
    int write_mask = (out_size >= c_elems + BB * QQ) ? 1 : 0;

    pseudo_kernel<<<(BB * QQ) / RPB, RPB * 32>>>(
        pred_logits_base, pred_boxes_base, targets_boxes,
        out + c_elems, write_mask);

    rows_kernel<<<dim3(IBLK, BB), RPB * 32>>>(
        pred_boxes, pred_logits, pred_boxes_base, out);
}